// round 1
// baseline (speedup 1.0000x reference)
#include <cuda_runtime.h>
#include <math.h>

#define IMH 256
#define IMW 320
#define HWSZ (IMH*IMW)
#define BB 4
#define HDIM 32
#define NCT 161

// ---------------- scratch (device globals; no allocation allowed) ----------
__device__ float g_z [BB*HDIM*HWSZ];
__device__ float g_rh[BB*HDIM*HWSZ];
__device__ float g_d2[BB*64*HWSZ];
// transposed weights: layout [(ic*9+tap)*32 + oc]
__device__ float g_wtz[NCT*9*32];
__device__ float g_wtr[NCT*9*32];
__device__ float g_wtq[NCT*9*32];
__device__ float g_wtd[32*9*32];
__device__ float g_wtc[32*9*32];

__device__ __forceinline__ float sigmoidf_(float v){ return 1.f/(1.f+__expf(-v)); }

// ---------------- weight transpose: [oc][ic][tap] -> [ic][tap][oc] ---------
__global__ void wtrans_kernel(const float* __restrict__ Wz, const float* __restrict__ Wr,
                              const float* __restrict__ Wq, const float* __restrict__ dh1,
                              const float* __restrict__ ch1){
  int t = blockIdx.y;
  int idx = blockIdx.x*256 + threadIdx.x;
  const float* src; float* dst; int cin;
  if      (t==0){src=Wz;  dst=g_wtz; cin=NCT;}
  else if (t==1){src=Wr;  dst=g_wtr; cin=NCT;}
  else if (t==2){src=Wq;  dst=g_wtq; cin=NCT;}
  else if (t==3){src=dh1; dst=g_wtd; cin=32;}
  else          {src=ch1; dst=g_wtc; cin=32;}
  int n = cin*288;
  if (idx < n){
    int ic = idx/288; int r = idx - ic*288; int tap = r>>5; int oc = r&31;
    dst[idx] = src[(oc*cin+ic)*9+tap];
  }
}

// ---------------- generic 3x3 conv, 32 out-channels, 4 px/thread ----------
// MODE 0: z = sigmoid(conv(hx,Wz)+bz)            -> g_z
// MODE 1: rh = sigmoid(conv(hx,Wr)+br)*hidden    -> g_rh
// MODE 2: q = tanh(conv([rh;x],Wq)+bq); h=(1-z)h0+zq -> out (h region)
// MODE 3: c1=relu(conv(h,ch1,dil2)); c0=ch2.c1+cb2 -> out(c0), out2(conf)
// MODE 4: d1=relu(conv(h,dh1,dil2)); d2=relu(dh2@d1) -> g_d2
template<int MODE>
__global__ void __launch_bounds__(128) conv_kernel(
    const float* __restrict__ in0, const float* __restrict__ in1, const float* __restrict__ in2,
    const float* __restrict__ bias, int Cin,
    const float* __restrict__ hidden, const float* __restrict__ aux, const float* __restrict__ aux2,
    float* __restrict__ out, float* __restrict__ out2)
{
  constexpr int DIL = (MODE>=3)?2:1;
  constexpr int SH = 16+2*DIL;
  constexpr int SW = 32+2*DIL;
  __shared__ float s_in[4*SH*SW];
  __shared__ float s_w[1152];
  __shared__ float s_dh2[(MODE==4)?2048:1];

  const int tid = threadIdx.x;
  const int x   = tid & 31;
  const int ty  = tid >> 5;
  const int ty4 = ty*4;
  const int x0  = blockIdx.x*32;
  const int y0  = blockIdx.y*16;
  const int b   = blockIdx.z;

  const float* i0 = in0;
  if (MODE==2) i0 = g_rh;
  const float* WtT;
  if      (MODE==0) WtT = g_wtz;
  else if (MODE==1) WtT = g_wtr;
  else if (MODE==2) WtT = g_wtq;
  else if (MODE==3) WtT = g_wtc;
  else              WtT = g_wtd;

  if (MODE==4){
    for (int i = tid; i < 2048; i += 128) s_dh2[i] = aux[i];
  }

  float acc[4][32];
  #pragma unroll
  for (int j=0;j<4;j++)
    #pragma unroll
    for (int o=0;o<32;o++) acc[j][o]=0.f;

  for (int c0=0; c0<Cin; c0+=4){
    // cooperative input tile load (4 channels, zero-padded)
    for (int idx = tid; idx < 4*SH*SW; idx += 128){
      int icl = idx/(SH*SW);
      int rem = idx - icl*(SH*SW);
      int sy  = rem/SW;
      int sx  = rem - sy*SW;
      int c   = c0+icl;
      int gy  = y0 + sy - DIL;
      int gx  = x0 + sx - DIL;
      float v = 0.f;
      if (c < Cin && (unsigned)gy < IMH && (unsigned)gx < IMW){
        const float* p;
        if (MODE>=3 || c < 32) p = i0 + (size_t)(b*32 + c)*HWSZ;
        else if (c == 32)      p = in1 + (size_t)b*HWSZ;
        else                   p = in2 + (size_t)(b*128 + (c-33))*HWSZ;
        v = p[gy*IMW + gx];
      }
      s_in[idx] = v;
    }
    // coalesced weight chunk load
    {
      int wbase = c0*288;
      int nrem  = (Cin - c0)*288;
      for (int idx = tid; idx < 1152; idx += 128)
        s_w[idx] = (idx < nrem) ? WtT[wbase + idx] : 0.f;
    }
    __syncthreads();

    for (int tap=0; tap<9; tap++){
      int dy = tap/3;
      int dx = tap - dy*3;
      #pragma unroll
      for (int icl=0; icl<4; icl++){
        int ibase = icl*(SH*SW) + (dy*DIL)*SW + x + dx*DIL;
        float v0 = s_in[ibase + (ty4+0)*SW];
        float v1 = s_in[ibase + (ty4+1)*SW];
        float v2 = s_in[ibase + (ty4+2)*SW];
        float v3 = s_in[ibase + (ty4+3)*SW];
        const float* wrow = &s_w[(icl*9+tap)*32];
        #pragma unroll
        for (int oc=0; oc<32; oc++){
          float w = wrow[oc];
          acc[0][oc] = fmaf(w, v0, acc[0][oc]);
          acc[1][oc] = fmaf(w, v1, acc[1][oc]);
          acc[2][oc] = fmaf(w, v2, acc[2][oc]);
          acc[3][oc] = fmaf(w, v3, acc[3][oc]);
        }
      }
    }
    __syncthreads();
  }

  const int xg = x0 + x;
  if (MODE==0 || MODE==1 || MODE==2){
    #pragma unroll
    for (int j=0;j<4;j++){
      int y = y0 + ty4 + j;
      #pragma unroll
      for (int oc=0; oc<32; oc++){
        int gidx = ((b*32+oc)*IMH + y)*IMW + xg;
        float v = acc[j][oc] + __ldg(bias+oc);
        if (MODE==0){
          g_z[gidx] = sigmoidf_(v);
        } else if (MODE==1){
          g_rh[gidx] = sigmoidf_(v) * __ldg(in0+gidx);
        } else {
          float q  = tanhf(v);
          float z  = g_z[gidx];
          float h0 = __ldg(hidden+gidx);
          out[gidx] = h0 + z*(q - h0);
        }
      }
    }
  } else if (MODE==3){
    float cb = __ldg(aux2);
    #pragma unroll
    for (int j=0;j<4;j++){
      int y = y0+ty4+j;
      float cv = cb;
      #pragma unroll
      for (int oc=0; oc<32; oc++)
        cv = fmaf(__ldg(aux+oc), fmaxf(acc[j][oc],0.f), cv);
      int pidx = (b*IMH + y)*IMW + xg;
      out [pidx] = cv;
      out2[pidx] = sigmoidf_(cv);
    }
  } else { // MODE 4
    #pragma unroll
    for (int j=0;j<4;j++){
      int y = y0+ty4+j;
      #pragma unroll
      for (int o=0;o<32;o++) acc[j][o] = fmaxf(acc[j][o], 0.f);
      for (int oc2=0; oc2<64; oc2++){
        float s = 0.f;
        const float* wr = &s_dh2[oc2*32];
        #pragma unroll
        for (int ic=0; ic<32; ic++) s = fmaf(wr[ic], acc[j][ic], s);
        g_d2[((b*64+oc2)*IMH + y)*IMW + xg] = fmaxf(s, 0.f);
      }
    }
  }
}

// ---------------- dh3 GEMM + softmax + argmax window regression -----------
// block = 256 thr, handles one (b,y) row; 5 tiles of 64 px.
__global__ void __launch_bounds__(256) head_kernel(
    const float* __restrict__ dh3, const float* __restrict__ db3,
    float* __restrict__ prob, float* __restrict__ nd)
{
  extern __shared__ float sm[];
  float* s_w3  = sm;            // 16384 : dh3 [256][64]
  float* s_db3 = sm + 16384;    // 256
  float* s_d2  = sm + 16640;    // 4096  : d2 [64][64]
  float* s_l   = sm + 20736;    // 16640 : logits/e [256][65]
  float* s_inv = sm + 37376;    // 64

  const int tid  = threadIdx.x;
  const int lane = tid & 31;
  const int g    = tid >> 5;
  const int y    = blockIdx.x;
  const int b    = blockIdx.y;

  for (int i = tid; i < 16384; i += 256) s_w3[i] = dh3[i];
  if (tid < 256) s_db3[tid] = db3[tid];
  __syncthreads();

  for (int xt = 0; xt < 5; xt++){
    int x0 = xt*64;
    for (int i = tid; i < 4096; i += 256){
      int ch = i >> 6, xp = i & 63;
      s_d2[i] = g_d2[((b*64+ch)*IMH + y)*IMW + x0 + xp];
    }
    __syncthreads();

    // logits: warp g computes oc [g*32, g*32+32) for pixels lane and lane+32
    {
      float a0[32], a1[32];
      #pragma unroll
      for (int o=0;o<32;o++){ a0[o]=0.f; a1[o]=0.f; }
      int x1 = lane, x2 = lane+32;
      #pragma unroll 4
      for (int ic=0; ic<64; ic++){
        float v0 = s_d2[ic*64 + x1];
        float v1 = s_d2[ic*64 + x2];
        const float* wr = &s_w3[(g*32)*64 + ic];
        #pragma unroll
        for (int oc=0; oc<32; oc++){
          float w = wr[oc*64];
          a0[oc] = fmaf(w, v0, a0[oc]);
          a1[oc] = fmaf(w, v1, a1[oc]);
        }
      }
      #pragma unroll
      for (int oc=0; oc<32; oc++){
        float bo = s_db3[g*32+oc];
        s_l[(g*32+oc)*65 + x1] = a0[oc] + bo;
        s_l[(g*32+oc)*65 + x2] = a1[oc] + bo;
      }
    }
    __syncthreads();

    // softmax + argmax window; warp g handles pixels [g*8, g*8+8)
    for (int p8 = 0; p8 < 8; p8++){
      int px = g*8 + p8;
      float lv[8];
      float m = -INFINITY; int mi = 0;
      #pragma unroll
      for (int k=0;k<8;k++){
        int oc = lane + k*32;
        lv[k] = s_l[oc*65 + px];
        if (lv[k] > m){ m = lv[k]; mi = oc; }
      }
      #pragma unroll
      for (int off=16; off; off>>=1){
        float om = __shfl_xor_sync(0xffffffffu, m,  off);
        int   oi = __shfl_xor_sync(0xffffffffu, mi, off);
        if (om > m || (om == m && oi < mi)){ m = om; mi = oi; }
      }
      float ssum = 0.f;
      #pragma unroll
      for (int k=0;k<8;k++){
        float e = __expf(lv[k] - m);
        s_l[(lane + k*32)*65 + px] = e;
        ssum += e;
      }
      #pragma unroll
      for (int off=16; off; off>>=1) ssum += __shfl_xor_sync(0xffffffffu, ssum, off);
      float inv = 1.f/ssum;
      __syncwarp();
      float aa = 0.f, bb = 0.f;
      if (lane < 9){
        int ocw = mi - 4 + lane;
        ocw = max(0, min(255, ocw));
        float pw = s_l[ocw*65 + px] * inv;
        aa = (float)ocw * pw;
        bb = pw;
      }
      #pragma unroll
      for (int off=16; off; off>>=1){
        aa += __shfl_xor_sync(0xffffffffu, aa, off);
        bb += __shfl_xor_sync(0xffffffffu, bb, off);
      }
      if (lane == 0){
        s_inv[px] = inv;
        nd[(b*IMH + y)*IMW + x0 + px] = (aa/(1e-6f + bb)) * (1.f/255.f);
      }
    }
    __syncthreads();

    // coalesced prob writeout
    for (int i = tid; i < 16384; i += 256){
      int oc = i >> 6, xp = i & 63;
      prob[((b*256+oc)*IMH + y)*IMW + x0 + xp] = s_l[oc*65 + xp] * s_inv[xp];
    }
    __syncthreads();
  }
}

// ---------------- launch ---------------------------------------------------
extern "C" void kernel_launch(void* const* d_in, const int* in_sizes, int n_in,
                              void* d_out, int out_size)
{
  const float* hidden = (const float*)d_in[0];
  const float* depth  = (const float*)d_in[1];
  const float* corr   = (const float*)d_in[2];
  const float* Wz  = (const float*)d_in[3];
  const float* bz  = (const float*)d_in[4];
  const float* Wr  = (const float*)d_in[5];
  const float* br  = (const float*)d_in[6];
  const float* Wq  = (const float*)d_in[7];
  const float* bq  = (const float*)d_in[8];
  const float* dh1 = (const float*)d_in[9];
  const float* dh2 = (const float*)d_in[10];
  const float* dh3 = (const float*)d_in[11];
  const float* db3 = (const float*)d_in[12];
  const float* ch1 = (const float*)d_in[13];
  const float* ch2 = (const float*)d_in[14];
  const float* cb2 = (const float*)d_in[15];

  float* out      = (float*)d_out;
  float* h_out    = out;
  float* nd_out   = h_out   + (size_t)BB*HDIM*HWSZ;   // 10,485,760
  float* prob_out = nd_out  + (size_t)BB*HWSZ;        // +327,680
  float* conf_out = prob_out+ (size_t)BB*256*HWSZ;    // +83,886,080
  float* c0_out   = conf_out+ (size_t)BB*HWSZ;        // +327,680

  dim3 tg(182, 5);
  wtrans_kernel<<<tg, 256>>>(Wz, Wr, Wq, dh1, ch1);

  dim3 cg(IMW/32, IMH/16, BB);
  conv_kernel<0><<<cg,128>>>(hidden, depth, corr, bz, NCT, nullptr, nullptr, nullptr, nullptr, nullptr);
  conv_kernel<1><<<cg,128>>>(hidden, depth, corr, br, NCT, nullptr, nullptr, nullptr, nullptr, nullptr);
  conv_kernel<2><<<cg,128>>>(nullptr, depth, corr, bq, NCT, hidden, nullptr, nullptr, h_out, nullptr);
  conv_kernel<3><<<cg,128>>>(h_out, nullptr, nullptr, nullptr, 32, nullptr, ch2, cb2, c0_out, conf_out);
  conv_kernel<4><<<cg,128>>>(h_out, nullptr, nullptr, nullptr, 32, nullptr, dh2, nullptr, nullptr, nullptr);

  cudaFuncSetAttribute(head_kernel, cudaFuncAttributeMaxDynamicSharedMemorySize, 149760);
  head_kernel<<<dim3(IMH, BB), 256, 149760>>>(dh3, db3, prob_out, nd_out);
}

// round 2
// speedup vs baseline: 1.5777x; 1.5777x over previous
#include <cuda_runtime.h>
#include <math.h>

#define IMH 256
#define IMW 320
#define HWSZ (IMH*IMW)
#define BB 4
#define HDIM 32
#define NCT 161

// ---------------- scratch (device globals; no allocation allowed) ----------
__device__ float g_z [BB*HDIM*HWSZ];
__device__ float g_rh[BB*HDIM*HWSZ];
__device__ float g_d2[BB*64*HWSZ];
// transposed weights: layout [(ic*9+tap)*32 + oc]
__device__ float g_wtz[NCT*9*32];
__device__ float g_wtr[NCT*9*32];
__device__ float g_wtq[NCT*9*32];
__device__ float g_wtd[32*9*32];
__device__ float g_wtc[32*9*32];

__device__ __forceinline__ float sigmoidf_(float v){ return 1.f/(1.f+__expf(-v)); }

// ---- packed fp32x2 helpers (sm_103a FFMA2 — PTX-only, ptxas won't fuse) ---
__device__ __forceinline__ unsigned long long pack2(float a, float b){
  unsigned long long r; asm("mov.b64 %0,{%1,%2};":"=l"(r):"f"(a),"f"(b)); return r;
}
__device__ __forceinline__ void ffma2(unsigned long long& d, unsigned long long a, unsigned long long b){
  asm("fma.rn.f32x2 %0, %1, %2, %0;":"+l"(d):"l"(a),"l"(b));
}
__device__ __forceinline__ float2 unpack2(unsigned long long v){
  float2 r; asm("mov.b64 {%0,%1}, %2;":"=f"(r.x),"=f"(r.y):"l"(v)); return r;
}

// ---------------- weight transpose: [oc][ic][tap] -> [ic][tap][oc] ---------
__global__ void wtrans_kernel(const float* __restrict__ Wz, const float* __restrict__ Wr,
                              const float* __restrict__ Wq, const float* __restrict__ dh1,
                              const float* __restrict__ ch1){
  int t = blockIdx.y;
  int idx = blockIdx.x*256 + threadIdx.x;
  const float* src; float* dst; int cin;
  if      (t==0){src=Wz;  dst=g_wtz; cin=NCT;}
  else if (t==1){src=Wr;  dst=g_wtr; cin=NCT;}
  else if (t==2){src=Wq;  dst=g_wtq; cin=NCT;}
  else if (t==3){src=dh1; dst=g_wtd; cin=32;}
  else          {src=ch1; dst=g_wtc; cin=32;}
  int n = cin*288;
  if (idx < n){
    int ic = idx/288; int r = idx - ic*288; int tap = r>>5; int oc = r&31;
    dst[idx] = src[(oc*cin+ic)*9+tap];
  }
}

// ============= GRU convs (Cin=161) — fp32x2, 256 thr, 4px x 16oc ==========
// MODE 0: z = sigmoid(conv(hx,Wz)+bz)                -> g_z
// MODE 1: rh = sigmoid(conv(hx,Wr)+br)*hidden        -> g_rh
// MODE 2: q = tanh(conv([rh;x],Wq)+bq); h=(1-z)h+zq  -> out
template<int MODE>
__global__ void __launch_bounds__(256,2) gru_conv(
    const float* __restrict__ in_h, const float* __restrict__ depth,
    const float* __restrict__ corr, const float* __restrict__ bias,
    const float* __restrict__ hidden, float* __restrict__ out)
{
  constexpr int SH = 18;
  constexpr int SW = 34;
  __shared__ __align__(16) float s_in[4*SH*SW];   // 2448
  __shared__ __align__(16) float s_w[1152];

  const int tid = threadIdx.x;
  const int x   = tid & 31;
  const int ty  = (tid >> 5) & 3;    // 4 row-groups of 4 rows
  const int oh  = tid >> 7;          // oc half: 0 or 1
  const int ty4 = ty*4;
  const int x0  = blockIdx.x*32;
  const int y0  = blockIdx.y*16;
  const int b   = blockIdx.z;

  const float* i0 = (MODE==2) ? (const float*)g_rh : in_h;
  const float* WtT = (MODE==0) ? g_wtz : ((MODE==1) ? g_wtr : g_wtq);

  unsigned long long acc[4][8];
  #pragma unroll
  for (int j=0;j<4;j++)
    #pragma unroll
    for (int o=0;o<8;o++) acc[j][o] = 0ull;

  for (int c0=0; c0<NCT; c0+=4){
    // cooperative input tile load (4 channels, zero-padded)
    for (int idx = tid; idx < 4*SH*SW; idx += 256){
      int icl = idx/(SH*SW);
      int rem = idx - icl*(SH*SW);
      int sy  = rem/SW;
      int sx  = rem - sy*SW;
      int c   = c0+icl;
      int gy  = y0 + sy - 1;
      int gx  = x0 + sx - 1;
      float v = 0.f;
      if (c < NCT && (unsigned)gy < IMH && (unsigned)gx < IMW){
        const float* p;
        if (c < 32)       p = i0 + (size_t)(b*32 + c)*HWSZ;
        else if (c == 32) p = depth + (size_t)b*HWSZ;
        else              p = corr + (size_t)(b*128 + (c-33))*HWSZ;
        v = p[gy*IMW + gx];
      }
      s_in[idx] = v;
    }
    {
      int wbase = c0*288;
      int nrem  = (NCT - c0)*288;
      for (int idx = tid; idx < 1152; idx += 256)
        s_w[idx] = (idx < nrem) ? WtT[wbase + idx] : 0.f;
    }
    __syncthreads();

    #pragma unroll
    for (int tap=0; tap<9; tap++){
      const int dy = tap/3;
      const int dx = tap - dy*3;
      #pragma unroll
      for (int icl=0; icl<4; icl++){
        int ibase = icl*(SH*SW) + dy*SW + x + dx;
        float v0 = s_in[ibase + (ty4+0)*SW];
        float v1 = s_in[ibase + (ty4+1)*SW];
        float v2 = s_in[ibase + (ty4+2)*SW];
        float v3 = s_in[ibase + (ty4+3)*SW];
        unsigned long long vv0 = pack2(v0,v0);
        unsigned long long vv1 = pack2(v1,v1);
        unsigned long long vv2 = pack2(v2,v2);
        unsigned long long vv3 = pack2(v3,v3);
        const float* wrow = &s_w[(icl*9+tap)*32 + oh*16];
        #pragma unroll
        for (int op=0; op<8; op++){
          unsigned long long wp = *(const unsigned long long*)(wrow + 2*op);
          ffma2(acc[0][op], vv0, wp);
          ffma2(acc[1][op], vv1, wp);
          ffma2(acc[2][op], vv2, wp);
          ffma2(acc[3][op], vv3, wp);
        }
      }
    }
    __syncthreads();
  }

  const int xg = x0 + x;
  #pragma unroll
  for (int j=0;j<4;j++){
    int y = y0 + ty4 + j;
    #pragma unroll
    for (int op=0; op<8; op++){
      int oc = oh*16 + 2*op;
      float2 a = unpack2(acc[j][op]);
      float b0 = __ldg(bias+oc);
      float b1 = __ldg(bias+oc+1);
      int g0 = ((b*32+oc)*IMH + y)*IMW + xg;
      int g1 = g0 + HWSZ;
      if (MODE==0){
        g_z[g0] = sigmoidf_(a.x + b0);
        g_z[g1] = sigmoidf_(a.y + b1);
      } else if (MODE==1){
        g_rh[g0] = sigmoidf_(a.x + b0) * __ldg(hidden+g0);
        g_rh[g1] = sigmoidf_(a.y + b1) * __ldg(hidden+g1);
      } else {
        float q0 = tanhf(a.x + b0);
        float q1 = tanhf(a.y + b1);
        float z0 = g_z[g0], z1 = g_z[g1];
        float h0 = __ldg(hidden+g0), h1 = __ldg(hidden+g1);
        out[g0] = h0 + z0*(q0 - h0);
        out[g1] = h1 + z1*(q1 - h1);
      }
    }
  }
}

// ============= head convs (Cin=32, dil=2) — unchanged from R1 ==============
// MODE 3: c1=relu(conv(h,ch1,dil2)); c0=ch2.c1+cb2 -> out(c0), out2(conf)
// MODE 4: d1=relu(conv(h,dh1,dil2)); d2=relu(dh2@d1) -> g_d2
template<int MODE>
__global__ void __launch_bounds__(128) conv_kernel(
    const float* __restrict__ in0,
    const float* __restrict__ aux, const float* __restrict__ aux2,
    float* __restrict__ out, float* __restrict__ out2)
{
  constexpr int DIL = 2;
  constexpr int SH = 16+2*DIL;
  constexpr int SW = 32+2*DIL;
  __shared__ float s_in[4*SH*SW];
  __shared__ float s_w[1152];
  __shared__ float s_dh2[(MODE==4)?2048:1];

  const int tid = threadIdx.x;
  const int x   = tid & 31;
  const int ty  = tid >> 5;
  const int ty4 = ty*4;
  const int x0  = blockIdx.x*32;
  const int y0  = blockIdx.y*16;
  const int b   = blockIdx.z;

  const float* WtT = (MODE==3) ? g_wtc : g_wtd;

  if (MODE==4){
    for (int i = tid; i < 2048; i += 128) s_dh2[i] = aux[i];
  }

  float acc[4][32];
  #pragma unroll
  for (int j=0;j<4;j++)
    #pragma unroll
    for (int o=0;o<32;o++) acc[j][o]=0.f;

  for (int c0=0; c0<32; c0+=4){
    for (int idx = tid; idx < 4*SH*SW; idx += 128){
      int icl = idx/(SH*SW);
      int rem = idx - icl*(SH*SW);
      int sy  = rem/SW;
      int sx  = rem - sy*SW;
      int c   = c0+icl;
      int gy  = y0 + sy - DIL;
      int gx  = x0 + sx - DIL;
      float v = 0.f;
      if ((unsigned)gy < IMH && (unsigned)gx < IMW){
        v = in0[(size_t)(b*32 + c)*HWSZ + gy*IMW + gx];
      }
      s_in[idx] = v;
    }
    {
      int wbase = c0*288;
      for (int idx = tid; idx < 1152; idx += 128)
        s_w[idx] = WtT[wbase + idx];
    }
    __syncthreads();

    for (int tap=0; tap<9; tap++){
      int dy = tap/3;
      int dx = tap - dy*3;
      #pragma unroll
      for (int icl=0; icl<4; icl++){
        int ibase = icl*(SH*SW) + (dy*DIL)*SW + x + dx*DIL;
        float v0 = s_in[ibase + (ty4+0)*SW];
        float v1 = s_in[ibase + (ty4+1)*SW];
        float v2 = s_in[ibase + (ty4+2)*SW];
        float v3 = s_in[ibase + (ty4+3)*SW];
        const float* wrow = &s_w[(icl*9+tap)*32];
        #pragma unroll
        for (int oc=0; oc<32; oc++){
          float w = wrow[oc];
          acc[0][oc] = fmaf(w, v0, acc[0][oc]);
          acc[1][oc] = fmaf(w, v1, acc[1][oc]);
          acc[2][oc] = fmaf(w, v2, acc[2][oc]);
          acc[3][oc] = fmaf(w, v3, acc[3][oc]);
        }
      }
    }
    __syncthreads();
  }

  const int xg = x0 + x;
  if (MODE==3){
    float cb = __ldg(aux2);
    #pragma unroll
    for (int j=0;j<4;j++){
      int y = y0+ty4+j;
      float cv = cb;
      #pragma unroll
      for (int oc=0; oc<32; oc++)
        cv = fmaf(__ldg(aux+oc), fmaxf(acc[j][oc],0.f), cv);
      int pidx = (b*IMH + y)*IMW + xg;
      out [pidx] = cv;
      out2[pidx] = sigmoidf_(cv);
    }
  } else { // MODE 4
    #pragma unroll
    for (int j=0;j<4;j++){
      int y = y0+ty4+j;
      #pragma unroll
      for (int o=0;o<32;o++) acc[j][o] = fmaxf(acc[j][o], 0.f);
      for (int oc2=0; oc2<64; oc2++){
        float s = 0.f;
        const float* wr = &s_dh2[oc2*32];
        #pragma unroll
        for (int ic=0; ic<32; ic++) s = fmaf(wr[ic], acc[j][ic], s);
        g_d2[((b*64+oc2)*IMH + y)*IMW + xg] = fmaxf(s, 0.f);
      }
    }
  }
}

// ---------------- dh3 GEMM + softmax + argmax window regression -----------
__global__ void __launch_bounds__(256) head_kernel(
    const float* __restrict__ dh3, const float* __restrict__ db3,
    float* __restrict__ prob, float* __restrict__ nd)
{
  extern __shared__ float sm[];
  float* s_w3  = sm;            // 16384 : dh3 [256][64]
  float* s_db3 = sm + 16384;    // 256
  float* s_d2  = sm + 16640;    // 4096  : d2 [64][64]
  float* s_l   = sm + 20736;    // 16640 : logits/e [256][65]
  float* s_inv = sm + 37376;    // 64

  const int tid  = threadIdx.x;
  const int lane = tid & 31;
  const int g    = tid >> 5;
  const int y    = blockIdx.x;
  const int b    = blockIdx.y;

  for (int i = tid; i < 16384; i += 256) s_w3[i] = dh3[i];
  if (tid < 256) s_db3[tid] = db3[tid];
  __syncthreads();

  for (int xt = 0; xt < 5; xt++){
    int x0 = xt*64;
    for (int i = tid; i < 4096; i += 256){
      int ch = i >> 6, xp = i & 63;
      s_d2[i] = g_d2[((b*64+ch)*IMH + y)*IMW + x0 + xp];
    }
    __syncthreads();

    {
      float a0[32], a1[32];
      #pragma unroll
      for (int o=0;o<32;o++){ a0[o]=0.f; a1[o]=0.f; }
      int x1 = lane, x2 = lane+32;
      #pragma unroll 4
      for (int ic=0; ic<64; ic++){
        float v0 = s_d2[ic*64 + x1];
        float v1 = s_d2[ic*64 + x2];
        const float* wr = &s_w3[(g*32)*64 + ic];
        #pragma unroll
        for (int oc=0; oc<32; oc++){
          float w = wr[oc*64];
          a0[oc] = fmaf(w, v0, a0[oc]);
          a1[oc] = fmaf(w, v1, a1[oc]);
        }
      }
      #pragma unroll
      for (int oc=0; oc<32; oc++){
        float bo = s_db3[g*32+oc];
        s_l[(g*32+oc)*65 + x1] = a0[oc] + bo;
        s_l[(g*32+oc)*65 + x2] = a1[oc] + bo;
      }
    }
    __syncthreads();

    for (int p8 = 0; p8 < 8; p8++){
      int px = g*8 + p8;
      float lv[8];
      float m = -INFINITY; int mi = 0;
      #pragma unroll
      for (int k=0;k<8;k++){
        int oc = lane + k*32;
        lv[k] = s_l[oc*65 + px];
        if (lv[k] > m){ m = lv[k]; mi = oc; }
      }
      #pragma unroll
      for (int off=16; off; off>>=1){
        float om = __shfl_xor_sync(0xffffffffu, m,  off);
        int   oi = __shfl_xor_sync(0xffffffffu, mi, off);
        if (om > m || (om == m && oi < mi)){ m = om; mi = oi; }
      }
      float ssum = 0.f;
      #pragma unroll
      for (int k=0;k<8;k++){
        float e = __expf(lv[k] - m);
        s_l[(lane + k*32)*65 + px] = e;
        ssum += e;
      }
      #pragma unroll
      for (int off=16; off; off>>=1) ssum += __shfl_xor_sync(0xffffffffu, ssum, off);
      float inv = 1.f/ssum;
      __syncwarp();
      float aa = 0.f, bb = 0.f;
      if (lane < 9){
        int ocw = mi - 4 + lane;
        ocw = max(0, min(255, ocw));
        float pw = s_l[ocw*65 + px] * inv;
        aa = (float)ocw * pw;
        bb = pw;
      }
      #pragma unroll
      for (int off=16; off; off>>=1){
        aa += __shfl_xor_sync(0xffffffffu, aa, off);
        bb += __shfl_xor_sync(0xffffffffu, bb, off);
      }
      if (lane == 0){
        s_inv[px] = inv;
        nd[(b*IMH + y)*IMW + x0 + px] = (aa/(1e-6f + bb)) * (1.f/255.f);
      }
    }
    __syncthreads();

    for (int i = tid; i < 16384; i += 256){
      int oc = i >> 6, xp = i & 63;
      prob[((b*256+oc)*IMH + y)*IMW + x0 + xp] = s_l[oc*65 + xp] * s_inv[xp];
    }
    __syncthreads();
  }
}

// ---------------- launch ---------------------------------------------------
extern "C" void kernel_launch(void* const* d_in, const int* in_sizes, int n_in,
                              void* d_out, int out_size)
{
  const float* hidden = (const float*)d_in[0];
  const float* depth  = (const float*)d_in[1];
  const float* corr   = (const float*)d_in[2];
  const float* Wz  = (const float*)d_in[3];
  const float* bz  = (const float*)d_in[4];
  const float* Wr  = (const float*)d_in[5];
  const float* br  = (const float*)d_in[6];
  const float* Wq  = (const float*)d_in[7];
  const float* bq  = (const float*)d_in[8];
  const float* dh1 = (const float*)d_in[9];
  const float* dh2 = (const float*)d_in[10];
  const float* dh3 = (const float*)d_in[11];
  const float* db3 = (const float*)d_in[12];
  const float* ch1 = (const float*)d_in[13];
  const float* ch2 = (const float*)d_in[14];
  const float* cb2 = (const float*)d_in[15];

  float* out      = (float*)d_out;
  float* h_out    = out;
  float* nd_out   = h_out   + (size_t)BB*HDIM*HWSZ;
  float* prob_out = nd_out  + (size_t)BB*HWSZ;
  float* conf_out = prob_out+ (size_t)BB*256*HWSZ;
  float* c0_out   = conf_out+ (size_t)BB*HWSZ;

  dim3 tg(182, 5);
  wtrans_kernel<<<tg, 256>>>(Wz, Wr, Wq, dh1, ch1);

  dim3 cg(IMW/32, IMH/16, BB);
  gru_conv<0><<<cg,256>>>(hidden, depth, corr, bz, hidden, nullptr);
  gru_conv<1><<<cg,256>>>(hidden, depth, corr, br, hidden, nullptr);
  gru_conv<2><<<cg,256>>>(nullptr, depth, corr, bq, hidden, h_out);

  conv_kernel<3><<<cg,128>>>(h_out, ch2, cb2, c0_out, conf_out);
  conv_kernel<4><<<cg,128>>>(h_out, dh2, nullptr, nullptr, nullptr);

  cudaFuncSetAttribute(head_kernel, cudaFuncAttributeMaxDynamicSharedMemorySize, 149760);
  head_kernel<<<dim3(IMH, BB), 256, 149760>>>(dh3, db3, prob_out, nd_out);
}

// round 4
// speedup vs baseline: 2.4942x; 1.5809x over previous
#include <cuda_runtime.h>
#include <math.h>

#define IMH 256
#define IMW 320
#define HWSZ (IMH*IMW)
#define BB 4
#define NCT 161

// ---------------- scratch (device globals; no allocation allowed) ----------
__device__ float g_z [BB*32*HWSZ];
__device__ float g_rh[BB*32*HWSZ];
__device__ float g_d1[BB*32*HWSZ];
// transposed weights: layout [(ic*9+tap)*32 + oc]
__device__ float g_wtz[NCT*9*32];
__device__ float g_wtr[NCT*9*32];
__device__ float g_wtq[NCT*9*32];
__device__ float g_wtd[32*9*32];
__device__ float g_wtc[32*9*32];
__device__ float g_wt2[32*64];    // dh2^T  [ic][oc2]
__device__ float g_wt3[64*256];   // dh3^T  [ic][oc]

__device__ __forceinline__ float sigmoidf_(float v){ return 1.f/(1.f+__expf(-v)); }

// ---- packed fp32x2 helpers (sm_103a FFMA2 — PTX-only) ---------------------
__device__ __forceinline__ unsigned long long pack2(float a, float b){
  unsigned long long r; asm("mov.b64 %0,{%1,%2};":"=l"(r):"f"(a),"f"(b)); return r;
}
__device__ __forceinline__ void ffma2(unsigned long long& d, unsigned long long a, unsigned long long b){
  asm("fma.rn.f32x2 %0, %1, %2, %0;":"+l"(d):"l"(a),"l"(b));
}
__device__ __forceinline__ float2 unpack2(unsigned long long v){
  float2 r; asm("mov.b64 {%0,%1}, %2;":"=f"(r.x),"=f"(r.y):"l"(v)); return r;
}

// ---- cp.async helpers -----------------------------------------------------
__device__ __forceinline__ void cp_async4(float* smem_dst, const float* gsrc, bool valid){
  unsigned int d = (unsigned int)__cvta_generic_to_shared(smem_dst);
  int sz = valid ? 4 : 0;
  asm volatile("cp.async.ca.shared.global [%0], [%1], 4, %2;\n" :: "r"(d), "l"(gsrc), "r"(sz));
}
__device__ __forceinline__ void cp_commit(){ asm volatile("cp.async.commit_group;\n"); }
template<int N> __device__ __forceinline__ void cp_wait(){ asm volatile("cp.async.wait_group %0;\n"::"n"(N)); }

// ---------------- weight transforms ---------------------------------------
__global__ void wtrans_kernel(const float* __restrict__ Wz, const float* __restrict__ Wr,
                              const float* __restrict__ Wq, const float* __restrict__ dh1,
                              const float* __restrict__ ch1, const float* __restrict__ dh2,
                              const float* __restrict__ dh3){
  int t = blockIdx.y;
  int idx = blockIdx.x*256 + threadIdx.x;
  if (t < 5){
    const float* src; float* dst; int cin;
    if      (t==0){src=Wz;  dst=g_wtz; cin=NCT;}
    else if (t==1){src=Wr;  dst=g_wtr; cin=NCT;}
    else if (t==2){src=Wq;  dst=g_wtq; cin=NCT;}
    else if (t==3){src=dh1; dst=g_wtd; cin=32;}
    else          {src=ch1; dst=g_wtc; cin=32;}
    int n = cin*288;
    if (idx < n){
      int ic = idx/288; int r = idx - ic*288; int tap = r>>5; int oc = r&31;
      dst[idx] = src[(oc*cin+ic)*9+tap];
    }
  } else if (t==5){
    if (idx < 2048) g_wt2[idx] = dh2[(idx&63)*32 + (idx>>6)];
  } else {
    if (idx < 16384) g_wt3[idx] = dh3[(idx&255)*64 + (idx>>8)];
  }
}

// ============= pipelined 3x3 conv, f32x2, 256 thr, 4px x 16oc =============
// MODE 0: z = sigmoid(conv(hx,Wz)+bz)                -> g_z
// MODE 1: rh = sigmoid(conv(hx,Wr)+br)*hidden        -> g_rh
// MODE 2: q = tanh(conv([rh;x],Wq)+bq); h=(1-z)h+zq  -> out
// MODE 3: c1=relu(conv(h,ch1,dil2)); c0=ch2.c1+cb2   -> out(c0), out2(conf)
// MODE 4: d1=relu(conv(h,dh1,dil2))                  -> g_d1
template<int MODE>
__global__ void __launch_bounds__(256,2) conv_pipe(
    const float* __restrict__ in_h, const float* __restrict__ depth,
    const float* __restrict__ corr, const float* __restrict__ bias,
    const float* __restrict__ hidden,
    const float* __restrict__ aux, const float* __restrict__ aux2,
    float* __restrict__ out, float* __restrict__ out2)
{
  constexpr int CIN = (MODE<3)?NCT:32;
  constexpr int DIL = (MODE<3)?1:2;
  constexpr int SH  = 16+2*DIL;
  constexpr int SW  = 32+2*DIL;
  constexpr int CH  = 8;
  constexpr int TILE = CH*SH*SW;
  constexpr int WCH  = CH*288;
  constexpr int NC   = (CIN+CH-1)/CH;

  extern __shared__ float sm[];
  float* s_in  = sm;                 // 2*TILE
  float* s_w   = sm + 2*TILE;        // 2*WCH
  float* s_red = s_w + 2*WCH;        // 512 (MODE 3 only)

  const int tid = threadIdx.x;
  const int x   = tid & 31;
  const int ty  = (tid >> 5) & 3;
  const int oh  = tid >> 7;
  const int ty4 = ty*4;
  const int x0  = blockIdx.x*32;
  const int y0  = blockIdx.y*16;
  const int b   = blockIdx.z;

  const float* i0 = (MODE==2) ? (const float*)g_rh : in_h;
  const float* WtT;
  if      (MODE==0) WtT = g_wtz;
  else if (MODE==1) WtT = g_wtr;
  else if (MODE==2) WtT = g_wtq;
  else if (MODE==3) WtT = g_wtc;
  else              WtT = g_wtd;

  // prefetch one chunk into buffer `buf`
  auto prefetch = [&](int cc, int buf){
    int c0 = cc*CH;
    float* din = s_in + buf*TILE;
    float* dw  = s_w  + buf*WCH;
    for (int idx = tid; idx < TILE; idx += 256){
      int icl = idx/(SH*SW);
      int rem = idx - icl*(SH*SW);
      int sy  = rem/SW;
      int sx  = rem - sy*SW;
      int c   = c0+icl;
      int gy  = y0 + sy - DIL;
      int gx  = x0 + sx - DIL;
      bool ok = (c < CIN) && ((unsigned)gy < IMH) && ((unsigned)gx < IMW);
      int cs  = ok ? c : 0;
      const float* p;
      if (MODE>=3)      p = in_h + (size_t)(b*32 + cs)*HWSZ;
      else if (cs < 32) p = i0   + (size_t)(b*32 + cs)*HWSZ;
      else if (cs == 32)p = depth+ (size_t)b*HWSZ;
      else              p = corr + (size_t)(b*128 + (cs-33))*HWSZ;
      int off = ok ? (gy*IMW + gx) : 0;
      cp_async4(din + idx, p + off, ok);
    }
    int wbase = c0*288;
    for (int idx = tid; idx < WCH; idx += 256){
      bool ok = (wbase + idx) < CIN*288;
      cp_async4(dw + idx, WtT + (ok ? wbase+idx : 0), ok);
    }
  };

  unsigned long long acc[4][8];
  #pragma unroll
  for (int j=0;j<4;j++)
    #pragma unroll
    for (int o=0;o<8;o++) acc[j][o] = 0ull;

  prefetch(0, 0); cp_commit();

  for (int cc=0; cc<NC; cc++){
    if (cc+1 < NC){ prefetch(cc+1, (cc+1)&1); cp_commit(); cp_wait<1>(); }
    else          { cp_wait<0>(); }
    __syncthreads();

    const float* sin = s_in + (cc&1)*TILE;
    const float* sw  = s_w  + (cc&1)*WCH;

    for (int dy=0; dy<3; dy++){
      #pragma unroll
      for (int dx=0; dx<3; dx++){
        #pragma unroll
        for (int icl=0; icl<CH; icl++){
          int ibase = icl*(SH*SW) + (dy*DIL)*SW + x + dx*DIL;
          float v0 = sin[ibase + (ty4+0)*SW];
          float v1 = sin[ibase + (ty4+1)*SW];
          float v2 = sin[ibase + (ty4+2)*SW];
          float v3 = sin[ibase + (ty4+3)*SW];
          unsigned long long vv0 = pack2(v0,v0);
          unsigned long long vv1 = pack2(v1,v1);
          unsigned long long vv2 = pack2(v2,v2);
          unsigned long long vv3 = pack2(v3,v3);
          const float* wrow = &sw[(icl*9 + dy*3 + dx)*32 + oh*16];
          #pragma unroll
          for (int op=0; op<8; op++){
            unsigned long long wp = *(const unsigned long long*)(wrow + 2*op);
            ffma2(acc[0][op], vv0, wp);
            ffma2(acc[1][op], vv1, wp);
            ffma2(acc[2][op], vv2, wp);
            ffma2(acc[3][op], vv3, wp);
          }
        }
      }
    }
    __syncthreads();
  }

  const int xg = x0 + x;
  if (MODE==0 || MODE==1 || MODE==2){
    #pragma unroll
    for (int j=0;j<4;j++){
      int y = y0 + ty4 + j;
      #pragma unroll
      for (int op=0; op<8; op++){
        int oc = oh*16 + 2*op;
        float2 a = unpack2(acc[j][op]);
        float b0 = __ldg(bias+oc);
        float b1 = __ldg(bias+oc+1);
        int g0 = ((b*32+oc)*IMH + y)*IMW + xg;
        int g1 = g0 + HWSZ;
        if (MODE==0){
          g_z[g0] = sigmoidf_(a.x + b0);
          g_z[g1] = sigmoidf_(a.y + b1);
        } else if (MODE==1){
          g_rh[g0] = sigmoidf_(a.x + b0) * __ldg(hidden+g0);
          g_rh[g1] = sigmoidf_(a.y + b1) * __ldg(hidden+g1);
        } else {
          float q0 = tanhf(a.x + b0);
          float q1 = tanhf(a.y + b1);
          float z0 = g_z[g0], z1 = g_z[g1];
          float h0 = __ldg(hidden+g0), h1 = __ldg(hidden+g1);
          out[g0] = h0 + z0*(q0 - h0);
          out[g1] = h1 + z1*(q1 - h1);
        }
      }
    }
  } else if (MODE==3){
    float part[4];
    #pragma unroll
    for (int j=0;j<4;j++){
      float cv = 0.f;
      #pragma unroll
      for (int op=0; op<8; op++){
        int oc = oh*16 + 2*op;
        float2 a = unpack2(acc[j][op]);
        cv = fmaf(__ldg(aux+oc),   fmaxf(a.x,0.f), cv);
        cv = fmaf(__ldg(aux+oc+1), fmaxf(a.y,0.f), cv);
      }
      part[j] = cv;
    }
    if (oh==0){
      #pragma unroll
      for (int j=0;j<4;j++) s_red[(ty4+j)*32 + x] = part[j];
    }
    __syncthreads();
    if (oh==1){
      float cb = __ldg(aux2);
      #pragma unroll
      for (int j=0;j<4;j++){
        int y = y0+ty4+j;
        float cv = part[j] + s_red[(ty4+j)*32 + x] + cb;
        int pidx = (b*IMH + y)*IMW + xg;
        out [pidx] = cv;
        out2[pidx] = sigmoidf_(cv);
      }
    }
  } else { // MODE 4: relu(d1) -> g_d1
    #pragma unroll
    for (int j=0;j<4;j++){
      int y = y0+ty4+j;
      #pragma unroll
      for (int op=0; op<8; op++){
        int oc = oh*16 + 2*op;
        float2 a = unpack2(acc[j][op]);
        int g0 = ((b*32+oc)*IMH + y)*IMW + xg;
        g_d1[g0]        = fmaxf(a.x, 0.f);
        g_d1[g0+HWSZ]   = fmaxf(a.y, 0.f);
      }
    }
  }
}

// ---------------- dh2 + dh3 GEMM + softmax + argmax regression ------------
__global__ void __launch_bounds__(256) head_kernel(
    const float* __restrict__ db3,
    float* __restrict__ prob, float* __restrict__ nd)
{
  extern __shared__ float sm[];
  float* s_w3t = sm;             // 16384 : dh3^T [64][256]
  float* s_w2t = sm + 16384;     // 2048  : dh2^T [32][64]
  float* s_db3 = sm + 18432;     // 256
  float* s_d1  = sm + 18688;     // 2048  : d1 [32][64]
  float* s_d2  = sm + 20736;     // 4096  : d2 [64][64]
  float* s_l   = sm + 24832;     // 16640 : logits/e [256][65]
  float* s_inv = sm + 41472;     // 64

  const int tid  = threadIdx.x;
  const int lane = tid & 31;
  const int g    = tid >> 5;
  const int y    = blockIdx.x;
  const int b    = blockIdx.y;

  for (int i = tid; i < 16384; i += 256) s_w3t[i] = g_wt3[i];
  for (int i = tid; i < 2048;  i += 256) s_w2t[i] = g_wt2[i];
  if (tid < 256) s_db3[tid] = db3[tid];
  __syncthreads();

  for (int xt = 0; xt < 5; xt++){
    int x0 = xt*64;
    // stage d1 tile [32][64]
    for (int i = tid; i < 2048; i += 256){
      int ch = i >> 6, xp = i & 63;
      s_d1[i] = g_d1[((b*32+ch)*IMH + y)*IMW + x0 + xp];
    }
    __syncthreads();

    // d2 = relu(dh2 @ d1): thread -> px = tid&63, oc2 group (tid>>6)*16
    {
      int px  = tid & 63;
      int grp = tid >> 6;
      unsigned long long a2[8];
      #pragma unroll
      for (int k=0;k<8;k++) a2[k]=0ull;
      #pragma unroll 4
      for (int ic=0; ic<32; ic++){
        float v = s_d1[ic*64 + px];
        unsigned long long vv = pack2(v,v);
        const float* wr = &s_w2t[ic*64 + grp*16];
        #pragma unroll
        for (int k=0;k<8;k++){
          unsigned long long wp = *(const unsigned long long*)(wr + 2*k);
          ffma2(a2[k], vv, wp);
        }
      }
      #pragma unroll
      for (int k=0;k<8;k++){
        float2 a = unpack2(a2[k]);
        int oc2 = grp*16 + 2*k;
        s_d2[oc2*64 + px]     = fmaxf(a.x, 0.f);
        s_d2[(oc2+1)*64 + px] = fmaxf(a.y, 0.f);
      }
    }
    __syncthreads();

    // logits: warp g -> oc [g*32, g*32+32), px lane & lane+32 (f32x2 pairs)
    {
      unsigned long long a0[16], a1[16];
      #pragma unroll
      for (int k=0;k<16;k++){ a0[k]=0ull; a1[k]=0ull; }
      int x1 = lane, x2 = lane+32;
      #pragma unroll 4
      for (int ic=0; ic<64; ic++){
        float v0 = s_d2[ic*64 + x1];
        float v1 = s_d2[ic*64 + x2];
        unsigned long long vv0 = pack2(v0,v0);
        unsigned long long vv1 = pack2(v1,v1);
        const float* wr = &s_w3t[ic*256 + g*32];
        #pragma unroll
        for (int k=0;k<16;k++){
          unsigned long long wp = *(const unsigned long long*)(wr + 2*k);
          ffma2(a0[k], vv0, wp);
          ffma2(a1[k], vv1, wp);
        }
      }
      #pragma unroll
      for (int k=0;k<16;k++){
        int oc = g*32 + 2*k;
        float2 p0 = unpack2(a0[k]);
        float2 p1 = unpack2(a1[k]);
        float ba = s_db3[oc], bb = s_db3[oc+1];
        s_l[oc*65 + x1]     = p0.x + ba;
        s_l[(oc+1)*65 + x1] = p0.y + bb;
        s_l[oc*65 + x2]     = p1.x + ba;
        s_l[(oc+1)*65 + x2] = p1.y + bb;
      }
    }
    __syncthreads();

    // softmax + argmax window; warp g handles pixels [g*8, g*8+8)
    for (int p8 = 0; p8 < 8; p8++){
      int px = g*8 + p8;
      float lv[8];
      float m = -INFINITY; int mi = 0;
      #pragma unroll
      for (int k=0;k<8;k++){
        int oc = lane + k*32;
        lv[k] = s_l[oc*65 + px];
        if (lv[k] > m){ m = lv[k]; mi = oc; }
      }
      #pragma unroll
      for (int off=16; off; off>>=1){
        float om = __shfl_xor_sync(0xffffffffu, m,  off);
        int   oi = __shfl_xor_sync(0xffffffffu, mi, off);
        if (om > m || (om == m && oi < mi)){ m = om; mi = oi; }
      }
      float ssum = 0.f;
      #pragma unroll
      for (int k=0;k<8;k++){
        float e = __expf(lv[k] - m);
        s_l[(lane + k*32)*65 + px] = e;
        ssum += e;
      }
      #pragma unroll
      for (int off=16; off; off>>=1) ssum += __shfl_xor_sync(0xffffffffu, ssum, off);
      float inv = 1.f/ssum;
      __syncwarp();
      float aa = 0.f, bb = 0.f;
      if (lane < 9){
        int ocw = mi - 4 + lane;
        ocw = max(0, min(255, ocw));
        float pw = s_l[ocw*65 + px] * inv;
        aa = (float)ocw * pw;
        bb = pw;
      }
      #pragma unroll
      for (int off=16; off; off>>=1){
        aa += __shfl_xor_sync(0xffffffffu, aa, off);
        bb += __shfl_xor_sync(0xffffffffu, bb, off);
      }
      if (lane == 0){
        s_inv[px] = inv;
        nd[(b*IMH + y)*IMW + x0 + px] = (aa/(1e-6f + bb)) * (1.f/255.f);
      }
    }
    __syncthreads();

    // coalesced prob writeout
    for (int i = tid; i < 16384; i += 256){
      int oc = i >> 6, xp = i & 63;
      prob[((b*256+oc)*IMH + y)*IMW + x0 + xp] = s_l[oc*65 + xp] * s_inv[xp];
    }
    __syncthreads();
  }
}

// ---------------- launch ---------------------------------------------------
extern "C" void kernel_launch(void* const* d_in, const int* in_sizes, int n_in,
                              void* d_out, int out_size)
{
  const float* hidden = (const float*)d_in[0];
  const float* depth  = (const float*)d_in[1];
  const float* corr   = (const float*)d_in[2];
  const float* Wz  = (const float*)d_in[3];
  const float* bz  = (const float*)d_in[4];
  const float* Wr  = (const float*)d_in[5];
  const float* br  = (const float*)d_in[6];
  const float* Wq  = (const float*)d_in[7];
  const float* bq  = (const float*)d_in[8];
  const float* dh1 = (const float*)d_in[9];
  const float* dh2 = (const float*)d_in[10];
  const float* dh3 = (const float*)d_in[11];
  const float* db3 = (const float*)d_in[12];
  const float* ch1 = (const float*)d_in[13];
  const float* ch2 = (const float*)d_in[14];
  const float* cb2 = (const float*)d_in[15];

  float* out      = (float*)d_out;
  float* h_out    = out;
  float* nd_out   = h_out   + (size_t)BB*32*HWSZ;
  float* prob_out = nd_out  + (size_t)BB*HWSZ;
  float* conf_out = prob_out+ (size_t)BB*256*HWSZ;
  float* c0_out   = conf_out+ (size_t)BB*HWSZ;

  // dynamic smem sizes (set unconditionally — no static state allowed)
  const int SM_GRU  = (2*(8*18*34) + 2*(8*288)) * 4;            // 57600
  const int SM_HEADC= (2*(8*20*36) + 2*(8*288) + 512) * 4;      // 66560
  cudaFuncSetAttribute(conv_pipe<0>, cudaFuncAttributeMaxDynamicSharedMemorySize, SM_GRU);
  cudaFuncSetAttribute(conv_pipe<1>, cudaFuncAttributeMaxDynamicSharedMemorySize, SM_GRU);
  cudaFuncSetAttribute(conv_pipe<2>, cudaFuncAttributeMaxDynamicSharedMemorySize, SM_GRU);
  cudaFuncSetAttribute(conv_pipe<3>, cudaFuncAttributeMaxDynamicSharedMemorySize, SM_HEADC);
  cudaFuncSetAttribute(conv_pipe<4>, cudaFuncAttributeMaxDynamicSharedMemorySize, SM_HEADC);
  cudaFuncSetAttribute(head_kernel,  cudaFuncAttributeMaxDynamicSharedMemorySize, 41536*4);

  dim3 tg(182, 7);
  wtrans_kernel<<<tg, 256>>>(Wz, Wr, Wq, dh1, ch1, dh2, dh3);

  dim3 cg(IMW/32, IMH/16, BB);
  conv_pipe<0><<<cg,256,SM_GRU>>>(hidden, depth, corr, bz, hidden, nullptr, nullptr, nullptr, nullptr);
  conv_pipe<1><<<cg,256,SM_GRU>>>(hidden, depth, corr, br, hidden, nullptr, nullptr, nullptr, nullptr);
  conv_pipe<2><<<cg,256,SM_GRU>>>(hidden, depth, corr, bq, hidden, nullptr, nullptr, h_out, nullptr);
  conv_pipe<3><<<cg,256,SM_HEADC>>>(h_out, nullptr, nullptr, nullptr, nullptr, ch2, cb2, c0_out, conf_out);
  conv_pipe<4><<<cg,256,SM_HEADC>>>(h_out, nullptr, nullptr, nullptr, nullptr, nullptr, nullptr, nullptr, nullptr);

  head_kernel<<<dim3(IMH, BB), 256, 41536*4>>>(db3, prob_out, nd_out);
}